// round 5
// baseline (speedup 1.0000x reference)
#include <cuda_runtime.h>

#define DD   16
#define HH   56
#define WW   56
#define PP   (DD*HH*WW)      // 50176
#define CIN  32
#define COUT 64
#define KK   27
#define COFF 81
#define DHW  PP
#define OWPAD 84
#define KCI  (KK*CIN)        // 864

__device__ float g_off [COFF * PP];        // offsets [c][p]
__device__ float g_wr  [KK * CIN * COUT];  // main weight [k][ci][co]
__device__ float g_owr [KK * CIN * OWPAD]; // offset weight [k][ci][c pad84]
__device__ float g_xt  [PP * CIN];         // x transposed: [voxel][ci] (ci innermost)
__device__ float g_samp[KCI * PP];         // sampled im2col: [k*32+ci][p]  (~174MB)

// ---- packed fp32x2 helpers ------------------------------------------------
__device__ __forceinline__ unsigned long long fma2(unsigned long long a,
                                                   unsigned long long b,
                                                   unsigned long long c) {
    unsigned long long d;
    asm("fma.rn.f32x2 %0, %1, %2, %3;" : "=l"(d) : "l"(a), "l"(b), "l"(c));
    return d;
}
__device__ __forceinline__ unsigned long long pack2(float s) {
    unsigned long long d;
    asm("mov.b64 %0, {%1, %1};" : "=l"(d) : "f"(s));
    return d;
}
__device__ __forceinline__ void unpack2(unsigned long long v, float& lo, float& hi) {
    asm("mov.b64 {%0, %1}, %2;" : "=f"(lo), "=f"(hi) : "l"(v));
}

// ---------------------------------------------------------------------------
// Init: rearrange weights
// ---------------------------------------------------------------------------
__global__ void init_kernel(const float* __restrict__ offw,
                            const float* __restrict__ w) {
    int i = blockIdx.x * blockDim.x + threadIdx.x;
    if (i < KK * CIN * OWPAD) {
        int c  = i % OWPAD;
        int t  = i / OWPAD;
        int ci = t % CIN;
        int k  = t / CIN;
        g_owr[i] = (c < COFF) ? offw[(c * CIN + ci) * KK + k] : 0.f;
    }
    if (i < KK * CIN * COUT) {
        int co = i % COUT;
        int t  = i / COUT;
        int ci = t % CIN;
        int k  = t / CIN;
        g_wr[i] = w[(co * CIN + ci) * KK + k];
    }
}

// ---------------------------------------------------------------------------
// Transpose x: [ci][v] -> xt[v][ci]  (32x32 smem tiles, conflict-free)
// ---------------------------------------------------------------------------
__global__ __launch_bounds__(256)
void transpose_kernel(const float* __restrict__ x) {
    __shared__ float tile[CIN][33];
    int v0 = blockIdx.x * 32;
    int t  = threadIdx.x;
    int a  = t & 31, g = t >> 5;              // 8 groups
#pragma unroll
    for (int cc = 0; cc < CIN; cc += 8)       // load: lane = voxel (coalesced)
        tile[cc + g][a] = __ldg(x + (cc + g) * PP + v0 + a);
    __syncthreads();
#pragma unroll
    for (int vv = 0; vv < 32; vv += 8)        // store: lane = ci (coalesced)
        g_xt[(v0 + vv + g) * CIN + a] = tile[a][vv + g];
}

// ---------------------------------------------------------------------------
// Stage 1: dense offset conv (R2 version, unchanged)
// ---------------------------------------------------------------------------
__global__ __launch_bounds__(128)
void offconv_kernel(const float* __restrict__ x, const float* __restrict__ ob) {
    __shared__ __align__(16) float ws[CIN * OWPAD];

    int tid   = threadIdx.x;
    int gwarp = blockIdx.x * 4 + (tid >> 5);
    int lane  = tid & 31;
    int p     = gwarp * 32 + lane;
    int zo    = p / (HH * WW);
    int r     = p - zo * (HH * WW);
    int yo    = r / WW;
    int xo    = r - yo * WW;

    unsigned long long acc2[OWPAD / 2];
#pragma unroll
    for (int c = 0; c < OWPAD / 2; c++) acc2[c] = 0ull;

#pragma unroll 1
    for (int k = 0; k < KK; k++) {
        __syncthreads();
        {
            const float4* src = (const float4*)(g_owr + k * CIN * OWPAD);
            float4* dst = (float4*)ws;
            for (int i = tid; i < (CIN * OWPAD) / 4; i += 128) dst[i] = src[i];
        }
        __syncthreads();

        int kz = k / 9, ky = (k / 3) % 3, kx = k % 3;
        int zi = zo + kz - 1, yi = yo + ky - 1, xi = xo + kx - 1;
        bool valid = ((unsigned)zi < DD) & ((unsigned)yi < HH) & ((unsigned)xi < WW);
        int xidx = (zi * HH + yi) * WW + xi;

#pragma unroll 4
        for (int ci = 0; ci < CIN; ci++) {
            float xv = valid ? __ldg(x + ci * DHW + xidx) : 0.f;
            unsigned long long xv2 = pack2(xv);
            const ulonglong2* wv = (const ulonglong2*)(ws + ci * OWPAD);
#pragma unroll
            for (int j = 0; j < OWPAD / 4; j++) {
                ulonglong2 w2 = wv[j];
                acc2[2*j+0] = fma2(xv2, w2.x, acc2[2*j+0]);
                acc2[2*j+1] = fma2(xv2, w2.y, acc2[2*j+1]);
            }
        }
    }

#pragma unroll
    for (int i = 0; i < OWPAD / 2; i++) {
        float lo, hi;
        unpack2(acc2[i], lo, hi);
        int c = 2 * i;
        if (c < COFF)     g_off[c * PP + p]       = lo + __ldg(ob + c);
        if (c + 1 < COFF) g_off[(c + 1) * PP + p] = hi + __ldg(ob + c + 1);
    }
}

// ---------------------------------------------------------------------------
// Stage 2a: sampling pass.  grid=(392, 27), block=128.
// Phase 1: lane=p computes trilinear weights + clamped corner bases -> smem.
// Phase 2: lane=ci gathers 8 perfectly-coalesced 128B lines per p, forms s.
// Phase 3: transpose via smem, store g_samp[k*32+ci][p] coalesced over p.
// Clamp + zero-weight gives exact zero-pad semantics (no fallback needed).
// ---------------------------------------------------------------------------
__global__ __launch_bounds__(128)
void sample_kernel() {
    __shared__ __align__(16) float4 wsm[128][2];
    __shared__ __align__(16) int4   ism[128][2];
    __shared__ float stile[128 * 33];

    int t     = threadIdx.x;
    int pbase = blockIdx.x * 128;
    int k     = blockIdx.y;
    int p     = pbase + t;

    // ---- Phase 1: per-p sampling geometry (coalesced over p) ----
    {
        int zo = p / (HH * WW);
        int r  = p - zo * (HH * WW);
        int yo = r / WW;
        int xo = r - yo * WW;
        int kz = k / 9, ky = (k / 3) % 3, kx = k % 3;
        float dz = __ldg(g_off + (3*k+0) * PP + p);
        float dy = __ldg(g_off + (3*k+1) * PP + p);
        float dx = __ldg(g_off + (3*k+2) * PP + p);
        float zc = (float)(zo + kz - 1) + dz;
        float yc = (float)(yo + ky - 1) + dy;
        float xc = (float)(xo + kx - 1) + dx;
        float zf = floorf(zc), yf = floorf(yc), xf = floorf(xc);
        float fz = zc - zf, fy = yc - yf, fx = xc - xf;
        int z0 = (int)zf, y0 = (int)yf, x0 = (int)xf;

        float w8[8]; int id8[8];
#pragma unroll
        for (int j = 0; j < 8; j++) {
            int dzc = (j >> 2) & 1, dyc = (j >> 1) & 1, dxc = j & 1;
            int zi = z0 + dzc, yi = y0 + dyc, xi = x0 + dxc;
            bool v = ((unsigned)zi < DD) & ((unsigned)yi < HH) & ((unsigned)xi < WW);
            float wz = dzc ? fz : 1.f - fz;
            float wy = dyc ? fy : 1.f - fy;
            float wx = dxc ? fx : 1.f - fx;
            w8[j] = v ? (wz * wy * wx) : 0.f;
            int zic = min(max(zi, 0), DD - 1);
            int yic = min(max(yi, 0), HH - 1);
            int xic = min(max(xi, 0), WW - 1);
            id8[j] = ((zic * HH + yic) * WW + xic) * CIN;   // element offset in xt
        }
        wsm[t][0] = make_float4(w8[0], w8[1], w8[2], w8[3]);
        wsm[t][1] = make_float4(w8[4], w8[5], w8[6], w8[7]);
        ism[t][0] = make_int4(id8[0], id8[1], id8[2], id8[3]);
        ism[t][1] = make_int4(id8[4], id8[5], id8[6], id8[7]);
    }
    __syncthreads();

    // ---- Phase 2: gather, lane = ci ----
    int wid = t >> 5, lane = t & 31;
#pragma unroll 4
    for (int pp = 0; pp < 32; pp++) {
        int tp = wid * 32 + pp;                 // uniform across warp
        float4 wa = wsm[tp][0], wb = wsm[tp][1];
        int4   ia = ism[tp][0], ib = ism[tp][1];
        float s;
        s  = wa.x * __ldg(g_xt + ia.x + lane);
        s += wa.y * __ldg(g_xt + ia.y + lane);
        s += wa.z * __ldg(g_xt + ia.z + lane);
        s += wa.w * __ldg(g_xt + ia.w + lane);
        s += wb.x * __ldg(g_xt + ib.x + lane);
        s += wb.y * __ldg(g_xt + ib.y + lane);
        s += wb.z * __ldg(g_xt + ib.z + lane);
        s += wb.w * __ldg(g_xt + ib.w + lane);
        stile[tp * 33 + lane] = s;
    }
    __syncthreads();

    // ---- Phase 3: store transposed, coalesced over p ----
#pragma unroll
    for (int ci = 0; ci < CIN; ci++)
        g_samp[(k * CIN + ci) * PP + p] = stile[t * 33 + ci];
}

// ---------------------------------------------------------------------------
// Stage 2b: coalesced GEMM  out[co][p] = sum_kci W[kci][co] * samp[kci][p] + b.
// grid=(392, 2): co split in halves of 32; block=128 (4 warps of 32 p).
// ---------------------------------------------------------------------------
__global__ __launch_bounds__(128)
void gemm_kernel(const float* __restrict__ bias, float* __restrict__ out) {
    int t      = threadIdx.x;
    int gwarp  = blockIdx.x * 4 + (t >> 5);
    int lane   = t & 31;
    int p      = gwarp * 32 + lane;
    int cobase = blockIdx.y * 32;

    unsigned long long acc2[16];
#pragma unroll
    for (int i = 0; i < 16; i++) acc2[i] = 0ull;

#pragma unroll 4
    for (int kci = 0; kci < KCI; kci++) {
        float s = __ldg(g_samp + kci * PP + p);                 // coalesced
        unsigned long long s2 = pack2(s);
        const ulonglong2* wv = (const ulonglong2*)(g_wr + kci * COUT + cobase);
#pragma unroll
        for (int j = 0; j < 8; j++) {                           // uniform LDG.128
            ulonglong2 w2 = __ldg(wv + j);
            acc2[2*j+0] = fma2(s2, w2.x, acc2[2*j+0]);
            acc2[2*j+1] = fma2(s2, w2.y, acc2[2*j+1]);
        }
    }

#pragma unroll
    for (int i = 0; i < 16; i++) {
        float lo, hi;
        unpack2(acc2[i], lo, hi);
        int co = cobase + 2 * i;
        out[(co+0) * PP + p] = lo + __ldg(bias + co + 0);
        out[(co+1) * PP + p] = hi + __ldg(bias + co + 1);
    }
}

// ---------------------------------------------------------------------------
extern "C" void kernel_launch(void* const* d_in, const int* in_sizes, int n_in,
                              void* d_out, int out_size) {
    const float* x    = (const float*)d_in[0];  // [32,16,56,56]
    const float* offw = (const float*)d_in[1];  // [81,32,3,3,3]
    const float* offb = (const float*)d_in[2];  // [81]
    const float* w    = (const float*)d_in[3];  // [64,32,3,3,3]
    const float* b    = (const float*)d_in[4];  // [64]
    float* out = (float*)d_out;                 // [64,16,56,56]

    init_kernel<<<(KK * CIN * OWPAD + 255) / 256, 256>>>(offw, w);
    transpose_kernel<<<PP / 32, 256>>>(x);
    offconv_kernel<<<392, 128>>>(x, offb);
    dim3 sgrid(PP / 128, KK);                   // 392 x 27
    sample_kernel<<<sgrid, 128>>>();
    dim3 ggrid(392, 2);
    gemm_kernel<<<ggrid, 128>>>(b, out);
}

// round 6
// speedup vs baseline: 1.4700x; 1.4700x over previous
#include <cuda_runtime.h>

#define DD   16
#define HH   56
#define WW   56
#define PP   (DD*HH*WW)      // 50176
#define CIN  32
#define COUT 64
#define KK   27
#define COFF 81
#define DHW  PP
#define OWPAD 84

__device__ float g_off [COFF * PP];        // offsets [c][p]
__device__ float g_wr  [KK * CIN * COUT];  // main weight [k][ci][co]
__device__ float g_owr [KK * CIN * OWPAD]; // offset weight [k][ci][c pad84]
__device__ float g_xt  [PP * CIN];         // x transposed: [voxel][ci] (ci innermost)

// ---- packed fp32x2 helpers ------------------------------------------------
__device__ __forceinline__ unsigned long long fma2(unsigned long long a,
                                                   unsigned long long b,
                                                   unsigned long long c) {
    unsigned long long d;
    asm("fma.rn.f32x2 %0, %1, %2, %3;" : "=l"(d) : "l"(a), "l"(b), "l"(c));
    return d;
}
__device__ __forceinline__ unsigned long long pack2(float s) {
    unsigned long long d;
    asm("mov.b64 %0, {%1, %1};" : "=l"(d) : "f"(s));
    return d;
}
__device__ __forceinline__ void unpack2(unsigned long long v, float& lo, float& hi) {
    asm("mov.b64 {%0, %1}, %2;" : "=f"(lo), "=f"(hi) : "l"(v));
}

// ---------------------------------------------------------------------------
// Init: rearrange weights
// ---------------------------------------------------------------------------
__global__ void init_kernel(const float* __restrict__ offw,
                            const float* __restrict__ w) {
    int i = blockIdx.x * blockDim.x + threadIdx.x;
    if (i < KK * CIN * OWPAD) {
        int c  = i % OWPAD;
        int t  = i / OWPAD;
        int ci = t % CIN;
        int k  = t / CIN;
        g_owr[i] = (c < COFF) ? offw[(c * CIN + ci) * KK + k] : 0.f;
    }
    if (i < KK * CIN * COUT) {
        int co = i % COUT;
        int t  = i / COUT;
        int ci = t % CIN;
        int k  = t / CIN;
        g_wr[i] = w[(co * CIN + ci) * KK + k];
    }
}

// ---------------------------------------------------------------------------
// Transpose x: [ci][v] -> xt[v][ci]  (32x32 smem tiles, conflict-free)
// ---------------------------------------------------------------------------
__global__ __launch_bounds__(256)
void transpose_kernel(const float* __restrict__ x) {
    __shared__ float tile[CIN][33];
    int v0 = blockIdx.x * 32;
    int t  = threadIdx.x;
    int a  = t & 31, g = t >> 5;
#pragma unroll
    for (int cc = 0; cc < CIN; cc += 8)
        tile[cc + g][a] = __ldg(x + (cc + g) * PP + v0 + a);
    __syncthreads();
#pragma unroll
    for (int vv = 0; vv < 32; vv += 8)
        g_xt[(v0 + vv + g) * CIN + a] = tile[a][vv + g];
}

// ---------------------------------------------------------------------------
// Stage 1: dense offset conv (R2 version, unchanged)
// ---------------------------------------------------------------------------
__global__ __launch_bounds__(128)
void offconv_kernel(const float* __restrict__ x, const float* __restrict__ ob) {
    __shared__ __align__(16) float ws[CIN * OWPAD];

    int tid   = threadIdx.x;
    int gwarp = blockIdx.x * 4 + (tid >> 5);
    int lane  = tid & 31;
    int p     = gwarp * 32 + lane;
    int zo    = p / (HH * WW);
    int r     = p - zo * (HH * WW);
    int yo    = r / WW;
    int xo    = r - yo * WW;

    unsigned long long acc2[OWPAD / 2];
#pragma unroll
    for (int c = 0; c < OWPAD / 2; c++) acc2[c] = 0ull;

#pragma unroll 1
    for (int k = 0; k < KK; k++) {
        __syncthreads();
        {
            const float4* src = (const float4*)(g_owr + k * CIN * OWPAD);
            float4* dst = (float4*)ws;
            for (int i = tid; i < (CIN * OWPAD) / 4; i += 128) dst[i] = src[i];
        }
        __syncthreads();

        int kz = k / 9, ky = (k / 3) % 3, kx = k % 3;
        int zi = zo + kz - 1, yi = yo + ky - 1, xi = xo + kx - 1;
        bool valid = ((unsigned)zi < DD) & ((unsigned)yi < HH) & ((unsigned)xi < WW);
        int xidx = (zi * HH + yi) * WW + xi;

#pragma unroll 4
        for (int ci = 0; ci < CIN; ci++) {
            float xv = valid ? __ldg(x + ci * DHW + xidx) : 0.f;
            unsigned long long xv2 = pack2(xv);
            const ulonglong2* wv = (const ulonglong2*)(ws + ci * OWPAD);
#pragma unroll
            for (int j = 0; j < OWPAD / 4; j++) {
                ulonglong2 w2 = wv[j];
                acc2[2*j+0] = fma2(xv2, w2.x, acc2[2*j+0]);
                acc2[2*j+1] = fma2(xv2, w2.y, acc2[2*j+1]);
            }
        }
    }

#pragma unroll
    for (int i = 0; i < OWPAD / 2; i++) {
        float lo, hi;
        unpack2(acc2[i], lo, hi);
        int c = 2 * i;
        if (c < COFF)     g_off[c * PP + p]       = lo + __ldg(ob + c);
        if (c + 1 < COFF) g_off[(c + 1) * PP + p] = hi + __ldg(ob + c + 1);
    }
}

// ---------------------------------------------------------------------------
// Stage 2 (fused): per k -- geometry (lane=p), coalesced gather (lane=ci),
// then GEMM accumulate (thread=p, 64 accs).  No materialization, no atomics.
// ---------------------------------------------------------------------------
__global__ __launch_bounds__(128)
void deform_fused_kernel(const float* __restrict__ bias, float* __restrict__ out) {
    __shared__ __align__(16) float4 wsm[128][2];       //  4 KB
    __shared__ __align__(16) int4   ism[128][2];       //  4 KB
    __shared__ float stile[128 * 33];                  // 16.9 KB
    __shared__ __align__(16) float ws[CIN * COUT];     //  8 KB

    int t   = threadIdx.x;
    int p   = blockIdx.x * 128 + t;
    int wid = t >> 5, lane = t & 31;

    int zo = p / (HH * WW);
    int r0 = p - zo * (HH * WW);
    int yo = r0 / WW;
    int xo = r0 - yo * WW;

    unsigned long long acc2[COUT / 2];
#pragma unroll
    for (int i = 0; i < COUT / 2; i++) acc2[i] = 0ull;

#pragma unroll 1
    for (int k = 0; k < KK; k++) {
        __syncthreads();   // all threads done with previous stile/ws

        // stage weights [ci][co] for this k: 512 float4
        {
            const float4* src = (const float4*)(g_wr + k * CIN * COUT);
            float4* dst = (float4*)ws;
#pragma unroll
            for (int i = 0; i < 4; i++) dst[t + 128 * i] = src[t + 128 * i];
        }

        // geometry for own p (coalesced g_off loads)
        {
            int kz = k / 9, ky = (k / 3) % 3, kx = k % 3;
            float dz = __ldg(g_off + (3*k+0) * PP + p);
            float dy = __ldg(g_off + (3*k+1) * PP + p);
            float dx = __ldg(g_off + (3*k+2) * PP + p);
            float zc = (float)(zo + kz - 1) + dz;
            float yc = (float)(yo + ky - 1) + dy;
            float xc = (float)(xo + kx - 1) + dx;
            float zf = floorf(zc), yf = floorf(yc), xf = floorf(xc);
            float fz = zc - zf, fy = yc - yf, fx = xc - xf;
            int z0 = (int)zf, y0 = (int)yf, x0 = (int)xf;

            float w8[8]; int id8[8];
#pragma unroll
            for (int j = 0; j < 8; j++) {
                int dzc = (j >> 2) & 1, dyc = (j >> 1) & 1, dxc = j & 1;
                int zi = z0 + dzc, yi = y0 + dyc, xi = x0 + dxc;
                bool v = ((unsigned)zi < DD) & ((unsigned)yi < HH) & ((unsigned)xi < WW);
                float wz = dzc ? fz : 1.f - fz;
                float wy = dyc ? fy : 1.f - fy;
                float wx = dxc ? fx : 1.f - fx;
                w8[j] = v ? (wz * wy * wx) : 0.f;
                int zic = min(max(zi, 0), DD - 1);
                int yic = min(max(yi, 0), HH - 1);
                int xic = min(max(xi, 0), WW - 1);
                id8[j] = ((zic * HH + yic) * WW + xic) * CIN;  // elt offset in xt
            }
            wsm[t][0] = make_float4(w8[0], w8[1], w8[2], w8[3]);
            wsm[t][1] = make_float4(w8[4], w8[5], w8[6], w8[7]);
            ism[t][0] = make_int4(id8[0], id8[1], id8[2], id8[3]);
            ism[t][1] = make_int4(id8[4], id8[5], id8[6], id8[7]);
        }
        __syncthreads();

        // gather: lane = ci, 8 perfectly-coalesced 128B-line loads per p
#pragma unroll 4
        for (int pp = 0; pp < 32; pp++) {
            int tp = wid * 32 + pp;                 // uniform across warp
            float4 wa = wsm[tp][0], wb = wsm[tp][1];
            int4   ia = ism[tp][0], ib = ism[tp][1];
            float s;
            s  = wa.x * __ldg(g_xt + ia.x + lane);
            s += wa.y * __ldg(g_xt + ia.y + lane);
            s += wa.z * __ldg(g_xt + ia.z + lane);
            s += wa.w * __ldg(g_xt + ia.w + lane);
            s += wb.x * __ldg(g_xt + ib.x + lane);
            s += wb.y * __ldg(g_xt + ib.y + lane);
            s += wb.z * __ldg(g_xt + ib.z + lane);
            s += wb.w * __ldg(g_xt + ib.w + lane);
            stile[tp * 33 + lane] = s;
        }
        __syncthreads();

        // GEMM accumulate: thread = own p. stile read pattern conflict-free.
#pragma unroll 4
        for (int ci = 0; ci < CIN; ci++) {
            unsigned long long s2 = pack2(stile[t * 33 + ci]);
            const ulonglong2* wv = (const ulonglong2*)(ws + ci * COUT);
#pragma unroll
            for (int j = 0; j < COUT / 4; j++) {
                ulonglong2 w2 = wv[j];
                acc2[2*j+0] = fma2(s2, w2.x, acc2[2*j+0]);
                acc2[2*j+1] = fma2(s2, w2.y, acc2[2*j+1]);
            }
        }
    }

#pragma unroll
    for (int i = 0; i < COUT / 2; i++) {
        float lo, hi;
        unpack2(acc2[i], lo, hi);
        out[(2*i+0) * PP + p] = lo + __ldg(bias + 2*i+0);
        out[(2*i+1) * PP + p] = hi + __ldg(bias + 2*i+1);
    }
}

// ---------------------------------------------------------------------------
extern "C" void kernel_launch(void* const* d_in, const int* in_sizes, int n_in,
                              void* d_out, int out_size) {
    const float* x    = (const float*)d_in[0];  // [32,16,56,56]
    const float* offw = (const float*)d_in[1];  // [81,32,3,3,3]
    const float* offb = (const float*)d_in[2];  // [81]
    const float* w    = (const float*)d_in[3];  // [64,32,3,3,3]
    const float* b    = (const float*)d_in[4];  // [64]
    float* out = (float*)d_out;                 // [64,16,56,56]

    init_kernel<<<(KK * CIN * OWPAD + 255) / 256, 256>>>(offw, w);
    transpose_kernel<<<PP / 32, 256>>>(x);
    offconv_kernel<<<392, 128>>>(x, offb);
    deform_fused_kernel<<<PP / 128, 128>>>(b, out);   // 392 blocks
}

// round 9
// speedup vs baseline: 1.6644x; 1.1322x over previous
#include <cuda_runtime.h>

#define DD   16
#define HH   56
#define WW   56
#define PP   (DD*HH*WW)      // 50176
#define CIN  32
#define COUT 64
#define KK   27
#define COFF 81
#define DHW  PP
#define OWPAD 84
#define KSPL 3               // k-groups
#define KPG  (KK/KSPL)       // 9 k per group

__device__ float g_off [COFF * PP];        // offsets [c][p]  (bias-preinit, REDG)
__device__ float g_wr  [KK * CIN * COUT];  // main weight [k][ci][co]
__device__ float g_owr [KK * CIN * OWPAD]; // offset weight [k][ci][c pad84]
__device__ float g_xt  [PP * CIN];         // x transposed: [voxel][ci]

// ---- packed fp32x2 helpers ------------------------------------------------
__device__ __forceinline__ unsigned long long fma2(unsigned long long a,
                                                   unsigned long long b,
                                                   unsigned long long c) {
    unsigned long long d;
    asm("fma.rn.f32x2 %0, %1, %2, %3;" : "=l"(d) : "l"(a), "l"(b), "l"(c));
    return d;
}
__device__ __forceinline__ unsigned long long pack2(float s) {
    unsigned long long d;
    asm("mov.b64 %0, {%1, %1};" : "=l"(d) : "f"(s));
    return d;
}
__device__ __forceinline__ void unpack2(unsigned long long v, float& lo, float& hi) {
    asm("mov.b64 {%0, %1}, %2;" : "=f"(lo), "=f"(hi) : "l"(v));
}

// ---------------------------------------------------------------------------
// Init: rearrange weights + preinit g_off (offset bias) and out (main bias)
// ---------------------------------------------------------------------------
__global__ void init_kernel(const float* __restrict__ offw,
                            const float* __restrict__ w,
                            const float* __restrict__ ob,
                            const float* __restrict__ bias,
                            float* __restrict__ out) {
    const int i = blockIdx.x * blockDim.x + threadIdx.x;
    if (i < KK * CIN * OWPAD) {
        const int c  = i % OWPAD;
        const int t  = i / OWPAD;
        const int ci = t % CIN;
        const int k  = t / CIN;
        g_owr[i] = (c < COFF) ? offw[(c * CIN + ci) * KK + k] : 0.f;
    }
    if (i < KK * CIN * COUT) {
        const int co = i % COUT;
        const int t  = i / COUT;
        const int ci = t % CIN;
        const int k  = t / CIN;
        g_wr[i] = w[(co * CIN + ci) * KK + k];
    }
    if (i < COFF * PP) g_off[i] = __ldg(ob + i / PP);
    if (i < COUT * PP) out[i]   = __ldg(bias + i / PP);
}

// ---------------------------------------------------------------------------
// Transpose x: [ci][v] -> xt[v][ci]
// ---------------------------------------------------------------------------
__global__ __launch_bounds__(256)
void transpose_kernel(const float* __restrict__ x) {
    __shared__ float tile[CIN][33];
    const int v0 = blockIdx.x * 32;
    const int t  = threadIdx.x;
    const int a  = t & 31, g = t >> 5;
#pragma unroll
    for (int cc = 0; cc < CIN; cc += 8)
        tile[cc + g][a] = __ldg(x + (cc + g) * PP + v0 + a);
    __syncthreads();
#pragma unroll
    for (int vv = 0; vv < 32; vv += 8)
        g_xt[(v0 + vv + g) * CIN + a] = tile[a][vv + g];
}

// ---------------------------------------------------------------------------
// Stage 1: dense offset conv, k-split x3.  grid (392, 3).
// ---------------------------------------------------------------------------
__global__ __launch_bounds__(128)
void offconv_kernel(const float* __restrict__ x) {
    __shared__ __align__(16) float ws[CIN * OWPAD];

    const int tid   = threadIdx.x;
    const int gwarp = blockIdx.x * 4 + (tid >> 5);
    const int lane  = tid & 31;
    const int p     = gwarp * 32 + lane;
    const int kbase = blockIdx.y * KPG;
    const int zo    = p / (HH * WW);
    const int r     = p - zo * (HH * WW);
    const int yo    = r / WW;
    const int xo    = r - yo * WW;

    unsigned long long acc2[OWPAD / 2];
#pragma unroll
    for (int c = 0; c < OWPAD / 2; c++) acc2[c] = 0ull;

#pragma unroll 1
    for (int kk = 0; kk < KPG; kk++) {
        const int k = kbase + kk;
        __syncthreads();
        {
            const float4* src = (const float4*)(g_owr + k * CIN * OWPAD);
            float4* dst = (float4*)ws;
            for (int i = tid; i < (CIN * OWPAD) / 4; i += 128) dst[i] = src[i];
        }
        __syncthreads();

        const int kz = k / 9, ky = (k / 3) % 3, kx = k % 3;
        const int zi = zo + kz - 1, yi = yo + ky - 1, xi = xo + kx - 1;
        const bool valid = ((unsigned)zi < DD) & ((unsigned)yi < HH) & ((unsigned)xi < WW);
        const int xidx = (zi * HH + yi) * WW + xi;

#pragma unroll 4
        for (int ci = 0; ci < CIN; ci++) {
            const float xv = valid ? __ldg(x + ci * DHW + xidx) : 0.f;
            const unsigned long long xv2 = pack2(xv);
            const ulonglong2* wv = (const ulonglong2*)(ws + ci * OWPAD);
#pragma unroll
            for (int j = 0; j < OWPAD / 4; j++) {
                const ulonglong2 w2 = wv[j];
                acc2[2*j+0] = fma2(xv2, w2.x, acc2[2*j+0]);
                acc2[2*j+1] = fma2(xv2, w2.y, acc2[2*j+1]);
            }
        }
    }

#pragma unroll
    for (int i = 0; i < OWPAD / 2; i++) {
        float lo, hi;
        unpack2(acc2[i], lo, hi);
        const int c = 2 * i;
        if (c < COFF)     atomicAdd(g_off + c * PP + p, lo);
        if (c + 1 < COFF) atomicAdd(g_off + (c + 1) * PP + p, hi);
    }
}

// ---------------------------------------------------------------------------
// Stage 2 (fused, k-split x3): grid (392, 3).
// Per k: geometry (lane=p) -> coalesced gather (lane=ci) -> GEMM (thread=p).
// ---------------------------------------------------------------------------
__global__ __launch_bounds__(128)
void deform_fused_kernel(float* __restrict__ out) {
    __shared__ __align__(16) float4 wsm[128][2];       //  4 KB
    __shared__ __align__(16) int4   ism[128][2];       //  4 KB
    __shared__ __align__(8)  float stile[128 * 34];    // 17.4 KB (even stride -> LDS.64)
    __shared__ __align__(16) float ws[CIN * COUT];     //  8 KB

    const int t     = threadIdx.x;
    const int p     = blockIdx.x * 128 + t;
    const int kbase = blockIdx.y * KPG;
    const int wid   = t >> 5, lane = t & 31;

    const int zo = p / (HH * WW);
    const int r0 = p - zo * (HH * WW);
    const int yo = r0 / WW;
    const int xo = r0 - yo * WW;

    unsigned long long acc2[COUT / 2];
#pragma unroll
    for (int i = 0; i < COUT / 2; i++) acc2[i] = 0ull;

#pragma unroll 1
    for (int kk = 0; kk < KPG; kk++) {
        const int k = kbase + kk;
        __syncthreads();

        // stage weights [ci][co] for this k
        {
            const float4* src = (const float4*)(g_wr + k * CIN * COUT);
            float4* dst = (float4*)ws;
#pragma unroll
            for (int i = 0; i < 4; i++) dst[t + 128 * i] = src[t + 128 * i];
        }

        // geometry for own p
        {
            const int kz = k / 9, ky = (k / 3) % 3, kx = k % 3;
            const float dz = __ldg(g_off + (3*k+0) * PP + p);
            const float dy = __ldg(g_off + (3*k+1) * PP + p);
            const float dx = __ldg(g_off + (3*k+2) * PP + p);
            const float zc = (float)(zo + kz - 1) + dz;
            const float yc = (float)(yo + ky - 1) + dy;
            const float xc = (float)(xo + kx - 1) + dx;
            const float zf = floorf(zc), yf = floorf(yc), xf = floorf(xc);
            const float fz = zc - zf, fy = yc - yf, fx = xc - xf;
            const int z0 = (int)zf, y0 = (int)yf, x0 = (int)xf;

            float w8[8]; int id8[8];
#pragma unroll
            for (int j = 0; j < 8; j++) {
                const int dzc = (j >> 2) & 1, dyc = (j >> 1) & 1, dxc = j & 1;
                const int zi = z0 + dzc, yi = y0 + dyc, xi = x0 + dxc;
                const bool v = ((unsigned)zi < DD) & ((unsigned)yi < HH) & ((unsigned)xi < WW);
                const float wz = dzc ? fz : 1.f - fz;
                const float wy = dyc ? fy : 1.f - fy;
                const float wx = dxc ? fx : 1.f - fx;
                w8[j] = v ? (wz * wy * wx) : 0.f;
                const int zic = min(max(zi, 0), DD - 1);
                const int yic = min(max(yi, 0), HH - 1);
                const int xic = min(max(xi, 0), WW - 1);
                id8[j] = ((zic * HH + yic) * WW + xic) * CIN;
            }
            wsm[t][0] = make_float4(w8[0], w8[1], w8[2], w8[3]);
            wsm[t][1] = make_float4(w8[4], w8[5], w8[6], w8[7]);
            ism[t][0] = make_int4(id8[0], id8[1], id8[2], id8[3]);
            ism[t][1] = make_int4(id8[4], id8[5], id8[6], id8[7]);
        }
        __syncthreads();

        // gather: lane = ci, 8 coalesced 128B-line loads per p
#pragma unroll 4
        for (int pp = 0; pp < 32; pp++) {
            const int tp = wid * 32 + pp;
            const float4 wa = wsm[tp][0], wb = wsm[tp][1];
            const int4   ia = ism[tp][0], ib = ism[tp][1];
            float s;
            s  = wa.x * __ldg(g_xt + ia.x + lane);
            s += wa.y * __ldg(g_xt + ia.y + lane);
            s += wa.z * __ldg(g_xt + ia.z + lane);
            s += wa.w * __ldg(g_xt + ia.w + lane);
            s += wb.x * __ldg(g_xt + ib.x + lane);
            s += wb.y * __ldg(g_xt + ib.y + lane);
            s += wb.z * __ldg(g_xt + ib.z + lane);
            s += wb.w * __ldg(g_xt + ib.w + lane);
            stile[tp * 34 + lane] = s;
        }
        __syncthreads();

        // GEMM accumulate: thread = own p; paired ci via LDS.64
#pragma unroll 4
        for (int ci = 0; ci < CIN; ci += 2) {
            const float2 sv = *(const float2*)(stile + t * 34 + ci);
            const unsigned long long sa = pack2(sv.x);
            const unsigned long long sb = pack2(sv.y);
            const ulonglong2* wva = (const ulonglong2*)(ws + ci * COUT);
            const ulonglong2* wvb = (const ulonglong2*)(ws + (ci + 1) * COUT);
#pragma unroll
            for (int j = 0; j < COUT / 4; j++) {
                const ulonglong2 w2a = wva[j];
                acc2[2*j+0] = fma2(sa, w2a.x, acc2[2*j+0]);
                acc2[2*j+1] = fma2(sa, w2a.y, acc2[2*j+1]);
            }
#pragma unroll
            for (int j = 0; j < COUT / 4; j++) {
                const ulonglong2 w2b = wvb[j];
                acc2[2*j+0] = fma2(sb, w2b.x, acc2[2*j+0]);
                acc2[2*j+1] = fma2(sb, w2b.y, acc2[2*j+1]);
            }
        }
    }

#pragma unroll
    for (int i = 0; i < COUT / 2; i++) {
        float lo, hi;
        unpack2(acc2[i], lo, hi);
        atomicAdd(out + (2*i+0) * PP + p, lo);
        atomicAdd(out + (2*i+1) * PP + p, hi);
    }
}

// ---------------------------------------------------------------------------
extern "C" void kernel_launch(void* const* d_in, const int* in_sizes, int n_in,
                              void* d_out, int out_size) {
    const float* x    = (const float*)d_in[0];  // [32,16,56,56]
    const float* offw = (const float*)d_in[1];  // [81,32,3,3,3]
    const float* offb = (const float*)d_in[2];  // [81]
    const float* w    = (const float*)d_in[3];  // [64,32,3,3,3]
    const float* b    = (const float*)d_in[4];  // [64]
    float* out = (float*)d_out;                 // [64,16,56,56]

    const int initN = (COFF * PP + 255) / 256;
    init_kernel<<<initN, 256>>>(offw, w, offb, b, out);
    transpose_kernel<<<PP / 32, 256>>>(x);
    const dim3 grid2(PP / 128, KSPL);
    offconv_kernel<<<grid2, 128>>>(x);
    deform_fused_kernel<<<grid2, 128>>>(out);
}

// round 10
// speedup vs baseline: 1.7828x; 1.0712x over previous
#include <cuda_runtime.h>

#define DD   16
#define HH   56
#define WW   56
#define PP   (DD*HH*WW)      // 50176
#define CIN  32
#define COUT 64
#define KK   27
#define COFF 81
#define DHW  PP
#define OWPAD 96             // 81 padded to 96 = 4 co-slices of 24
#define KSPL 3               // k-groups
#define KPG  (KK/KSPL)       // 9 k per group

__device__ float g_off [COFF * PP];        // offsets [c][p]  (bias-preinit, REDG)
__device__ float g_wr  [KK * CIN * COUT];  // main weight [k][ci][co]
__device__ float g_owr [KK * CIN * OWPAD]; // offset weight [k][ci][c pad96]
__device__ float g_xt  [PP * CIN];         // x transposed: [voxel][ci]

// ---- packed fp32x2 helpers ------------------------------------------------
__device__ __forceinline__ unsigned long long fma2(unsigned long long a,
                                                   unsigned long long b,
                                                   unsigned long long c) {
    unsigned long long d;
    asm("fma.rn.f32x2 %0, %1, %2, %3;" : "=l"(d) : "l"(a), "l"(b), "l"(c));
    return d;
}
__device__ __forceinline__ unsigned long long pack2(float s) {
    unsigned long long d;
    asm("mov.b64 %0, {%1, %1};" : "=l"(d) : "f"(s));
    return d;
}
__device__ __forceinline__ void unpack2(unsigned long long v, float& lo, float& hi) {
    asm("mov.b64 {%0, %1}, %2;" : "=f"(lo), "=f"(hi) : "l"(v));
}

// ---------------------------------------------------------------------------
// Init: rearrange weights + preinit g_off (offset bias) and out (main bias)
// ---------------------------------------------------------------------------
__global__ void init_kernel(const float* __restrict__ offw,
                            const float* __restrict__ w,
                            const float* __restrict__ ob,
                            const float* __restrict__ bias,
                            float* __restrict__ out) {
    const int i = blockIdx.x * blockDim.x + threadIdx.x;
    if (i < KK * CIN * OWPAD) {
        const int c  = i % OWPAD;
        const int t  = i / OWPAD;
        const int ci = t % CIN;
        const int k  = t / CIN;
        g_owr[i] = (c < COFF) ? offw[(c * CIN + ci) * KK + k] : 0.f;
    }
    if (i < KK * CIN * COUT) {
        const int co = i % COUT;
        const int t  = i / COUT;
        const int ci = t % CIN;
        const int k  = t / CIN;
        g_wr[i] = w[(co * CIN + ci) * KK + k];
    }
    if (i < COFF * PP) g_off[i] = __ldg(ob + i / PP);
    if (i < COUT * PP) out[i]   = __ldg(bias + i / PP);
}

// ---------------------------------------------------------------------------
// Transpose x: [ci][v] -> xt[v][ci]
// ---------------------------------------------------------------------------
__global__ __launch_bounds__(256)
void transpose_kernel(const float* __restrict__ x) {
    __shared__ float tile[CIN][33];
    const int v0 = blockIdx.x * 32;
    const int t  = threadIdx.x;
    const int a  = t & 31, g = t >> 5;
#pragma unroll
    for (int cc = 0; cc < CIN; cc += 8)
        tile[cc + g][a] = __ldg(x + (cc + g) * PP + v0 + a);
    __syncthreads();
#pragma unroll
    for (int vv = 0; vv < 32; vv += 8)
        g_xt[(v0 + vv + g) * CIN + a] = tile[a][vv + g];
}

// ---------------------------------------------------------------------------
// Stage 1: dense offset conv, k-split x3, co-distributed weights.
// Lane = (pg 0..7, cg 0..3); thread owns 4 p (= base+4pg+j) x 24 co slice.
// xv loaded coalesced (lane = own p) then redistributed via shfl.
// ---------------------------------------------------------------------------
__global__ __launch_bounds__(128)
void offconv_kernel(const float* __restrict__ x) {
    __shared__ __align__(16) float ws[CIN * OWPAD];   // 12 KB

    const int tid   = threadIdx.x;
    const int lane  = tid & 31;
    const int wbase = blockIdx.x * 128 + (tid >> 5) * 32;  // warp's 32-p range
    const int pown  = wbase + lane;                        // p used for xv load
    const int kbase = blockIdx.y * KPG;
    const int pg    = lane & 7;
    const int cg    = lane >> 3;                           // 0..3, co slice 24*cg

    // geometry of own p (for xv load)
    const int zo = pown / (HH * WW);
    const int r  = pown - zo * (HH * WW);
    const int yo = r / WW;
    const int xo = r - yo * WW;

    unsigned long long acc2[48];   // [j 0..3][m 0..11] -> co = 24*cg + 2m(+1)
#pragma unroll
    for (int i = 0; i < 48; i++) acc2[i] = 0ull;

#pragma unroll 1
    for (int kk = 0; kk < KPG; kk++) {
        const int k = kbase + kk;
        __syncthreads();
        {   // stage weights for this k: 32*96 floats = 768 float4
            const float4* src = (const float4*)(g_owr + k * CIN * OWPAD);
            float4* dst = (float4*)ws;
#pragma unroll
            for (int i = 0; i < 6; i++) dst[tid + 128 * i] = src[tid + 128 * i];
        }
        __syncthreads();

        const int kz = k / 9, ky = (k / 3) % 3, kx = k % 3;
        const int zi = zo + kz - 1, yi = yo + ky - 1, xi = xo + kx - 1;
        const bool valid = ((unsigned)zi < DD) & ((unsigned)yi < HH) & ((unsigned)xi < WW);
        const int xidx = (zi * HH + yi) * WW + xi;

#pragma unroll 2
        for (int ci = 0; ci < CIN; ci++) {
            const float xv_own = valid ? __ldg(x + ci * DHW + xidx) : 0.f;
            unsigned long long xv2[4];
#pragma unroll
            for (int j = 0; j < 4; j++)
                xv2[j] = pack2(__shfl_sync(0xffffffffu, xv_own, 4 * pg + j));
            const ulonglong2* wv = (const ulonglong2*)(ws + ci * OWPAD + 24 * cg);
#pragma unroll
            for (int jj = 0; jj < 6; jj++) {          // 6 LDS.128, 1 wf each
                const ulonglong2 w2 = wv[jj];
#pragma unroll
                for (int j = 0; j < 4; j++) {
                    acc2[j * 12 + jj * 2 + 0] = fma2(xv2[j], w2.x, acc2[j * 12 + jj * 2 + 0]);
                    acc2[j * 12 + jj * 2 + 1] = fma2(xv2[j], w2.y, acc2[j * 12 + jj * 2 + 1]);
                }
            }
        }
    }

#pragma unroll
    for (int j = 0; j < 4; j++) {
        const int p = wbase + 4 * pg + j;
#pragma unroll
        for (int m = 0; m < 12; m++) {
            float lo, hi;
            unpack2(acc2[j * 12 + m], lo, hi);
            const int c = 24 * cg + 2 * m;
            if (c < COFF)     atomicAdd(g_off + c * PP + p, lo);
            if (c + 1 < COFF) atomicAdd(g_off + (c + 1) * PP + p, hi);
        }
    }
}

// ---------------------------------------------------------------------------
// Stage 2 (fused, k-split x3): grid (392, 3)  — unchanged from R9.
// Per k: geometry (lane=p) -> coalesced gather (lane=ci) -> GEMM (thread=p).
// ---------------------------------------------------------------------------
__global__ __launch_bounds__(128)
void deform_fused_kernel(float* __restrict__ out) {
    __shared__ __align__(16) float4 wsm[128][2];       //  4 KB
    __shared__ __align__(16) int4   ism[128][2];       //  4 KB
    __shared__ __align__(8)  float stile[128 * 34];    // 17.4 KB
    __shared__ __align__(16) float ws[CIN * COUT];     //  8 KB

    const int t     = threadIdx.x;
    const int p     = blockIdx.x * 128 + t;
    const int kbase = blockIdx.y * KPG;
    const int wid   = t >> 5, lane = t & 31;

    const int zo = p / (HH * WW);
    const int r0 = p - zo * (HH * WW);
    const int yo = r0 / WW;
    const int xo = r0 - yo * WW;

    unsigned long long acc2[COUT / 2];
#pragma unroll
    for (int i = 0; i < COUT / 2; i++) acc2[i] = 0ull;

#pragma unroll 1
    for (int kk = 0; kk < KPG; kk++) {
        const int k = kbase + kk;
        __syncthreads();

        {   // stage weights [ci][co] for this k
            const float4* src = (const float4*)(g_wr + k * CIN * COUT);
            float4* dst = (float4*)ws;
#pragma unroll
            for (int i = 0; i < 4; i++) dst[t + 128 * i] = src[t + 128 * i];
        }

        {   // geometry for own p
            const int kz = k / 9, ky = (k / 3) % 3, kx = k % 3;
            const float dz = __ldg(g_off + (3*k+0) * PP + p);
            const float dy = __ldg(g_off + (3*k+1) * PP + p);
            const float dx = __ldg(g_off + (3*k+2) * PP + p);
            const float zc = (float)(zo + kz - 1) + dz;
            const float yc = (float)(yo + ky - 1) + dy;
            const float xc = (float)(xo + kx - 1) + dx;
            const float zf = floorf(zc), yf = floorf(yc), xf = floorf(xc);
            const float fz = zc - zf, fy = yc - yf, fx = xc - xf;
            const int z0 = (int)zf, y0 = (int)yf, x0 = (int)xf;

            float w8[8]; int id8[8];
#pragma unroll
            for (int j = 0; j < 8; j++) {
                const int dzc = (j >> 2) & 1, dyc = (j >> 1) & 1, dxc = j & 1;
                const int zi = z0 + dzc, yi = y0 + dyc, xi = x0 + dxc;
                const bool v = ((unsigned)zi < DD) & ((unsigned)yi < HH) & ((unsigned)xi < WW);
                const float wz = dzc ? fz : 1.f - fz;
                const float wy = dyc ? fy : 1.f - fy;
                const float wx = dxc ? fx : 1.f - fx;
                w8[j] = v ? (wz * wy * wx) : 0.f;
                const int zic = min(max(zi, 0), DD - 1);
                const int yic = min(max(yi, 0), HH - 1);
                const int xic = min(max(xi, 0), WW - 1);
                id8[j] = ((zic * HH + yic) * WW + xic) * CIN;
            }
            wsm[t][0] = make_float4(w8[0], w8[1], w8[2], w8[3]);
            wsm[t][1] = make_float4(w8[4], w8[5], w8[6], w8[7]);
            ism[t][0] = make_int4(id8[0], id8[1], id8[2], id8[3]);
            ism[t][1] = make_int4(id8[4], id8[5], id8[6], id8[7]);
        }
        __syncthreads();

        // gather: lane = ci, 8 coalesced 128B-line loads per p
#pragma unroll 4
        for (int pp = 0; pp < 32; pp++) {
            const int tp = wid * 32 + pp;
            const float4 wa = wsm[tp][0], wb = wsm[tp][1];
            const int4   ia = ism[tp][0], ib = ism[tp][1];
            float s;
            s  = wa.x * __ldg(g_xt + ia.x + lane);
            s += wa.y * __ldg(g_xt + ia.y + lane);
            s += wa.z * __ldg(g_xt + ia.z + lane);
            s += wa.w * __ldg(g_xt + ia.w + lane);
            s += wb.x * __ldg(g_xt + ib.x + lane);
            s += wb.y * __ldg(g_xt + ib.y + lane);
            s += wb.z * __ldg(g_xt + ib.z + lane);
            s += wb.w * __ldg(g_xt + ib.w + lane);
            stile[tp * 34 + lane] = s;
        }
        __syncthreads();

        // GEMM accumulate: thread = own p; paired ci via LDS.64
#pragma unroll 4
        for (int ci = 0; ci < CIN; ci += 2) {
            const float2 sv = *(const float2*)(stile + t * 34 + ci);
            const unsigned long long sa = pack2(sv.x);
            const unsigned long long sb = pack2(sv.y);
            const ulonglong2* wva = (const ulonglong2*)(ws + ci * COUT);
            const ulonglong2* wvb = (const ulonglong2*)(ws + (ci + 1) * COUT);
#pragma unroll
            for (int j = 0; j < COUT / 4; j++) {
                const ulonglong2 w2a = wva[j];
                acc2[2*j+0] = fma2(sa, w2a.x, acc2[2*j+0]);
                acc2[2*j+1] = fma2(sa, w2a.y, acc2[2*j+1]);
            }
#pragma unroll
            for (int j = 0; j < COUT / 4; j++) {
                const ulonglong2 w2b = wvb[j];
                acc2[2*j+0] = fma2(sb, w2b.x, acc2[2*j+0]);
                acc2[2*j+1] = fma2(sb, w2b.y, acc2[2*j+1]);
            }
        }
    }

#pragma unroll
    for (int i = 0; i < COUT / 2; i++) {
        float lo, hi;
        unpack2(acc2[i], lo, hi);
        atomicAdd(out + (2*i+0) * PP + p, lo);
        atomicAdd(out + (2*i+1) * PP + p, hi);
    }
}

// ---------------------------------------------------------------------------
extern "C" void kernel_launch(void* const* d_in, const int* in_sizes, int n_in,
                              void* d_out, int out_size) {
    const float* x    = (const float*)d_in[0];  // [32,16,56,56]
    const float* offw = (const float*)d_in[1];  // [81,32,3,3,3]
    const float* offb = (const float*)d_in[2];  // [81]
    const float* w    = (const float*)d_in[3];  // [64,32,3,3,3]
    const float* b    = (const float*)d_in[4];  // [64]
    float* out = (float*)d_out;                 // [64,16,56,56]

    const int initN = (COFF * PP + 255) / 256;
    init_kernel<<<initN, 256>>>(offw, w, offb, b, out);
    transpose_kernel<<<PP / 32, 256>>>(x);
    const dim3 grid2(PP / 128, KSPL);
    offconv_kernel<<<grid2, 128>>>(x);
    deform_fused_kernel<<<grid2, 128>>>(out);
}

// round 12
// speedup vs baseline: 1.9894x; 1.1159x over previous
#include <cuda_runtime.h>

#define DD   16
#define HH   56
#define WW   56
#define PP   (DD*HH*WW)      // 50176
#define CIN  32
#define COUT 64
#define KK   27
#define COFF 81
#define DHW  PP
#define OWPAD 96             // 81 padded to 96 = 4 co-slices of 24
#define KSPL 3               // k-groups
#define KPG  (KK/KSPL)       // 9 k per group
#define STR  129             // stile row stride (odd mod 32 -> conflict-free col writes)

__device__ float g_off [COFF * PP];        // offsets [c][p]  (bias-preinit, REDG)
__device__ float g_wr  [KK * CIN * COUT];  // main weight [k][ci][co]
__device__ float g_owr [KK * CIN * OWPAD]; // offset weight [k][ci][c pad96]
__device__ float g_xt  [PP * CIN];         // x transposed: [voxel][ci]

// ---- packed fp32x2 helpers ------------------------------------------------
__device__ __forceinline__ unsigned long long fma2(unsigned long long a,
                                                   unsigned long long b,
                                                   unsigned long long c) {
    unsigned long long d;
    asm("fma.rn.f32x2 %0, %1, %2, %3;" : "=l"(d) : "l"(a), "l"(b), "l"(c));
    return d;
}
__device__ __forceinline__ unsigned long long pack2(float s) {
    unsigned long long d;
    asm("mov.b64 %0, {%1, %1};" : "=l"(d) : "f"(s));
    return d;
}
__device__ __forceinline__ void unpack2(unsigned long long v, float& lo, float& hi) {
    asm("mov.b64 {%0, %1}, %2;" : "=f"(lo), "=f"(hi) : "l"(v));
}

// ---------------------------------------------------------------------------
// Init: rearrange weights + preinit g_off (offset bias) and out (main bias)
// ---------------------------------------------------------------------------
__global__ void init_kernel(const float* __restrict__ offw,
                            const float* __restrict__ w,
                            const float* __restrict__ ob,
                            const float* __restrict__ bias,
                            float* __restrict__ out) {
    const int i = blockIdx.x * blockDim.x + threadIdx.x;
    if (i < KK * CIN * OWPAD) {
        const int c  = i % OWPAD;
        const int t  = i / OWPAD;
        const int ci = t % CIN;
        const int k  = t / CIN;
        g_owr[i] = (c < COFF) ? offw[(c * CIN + ci) * KK + k] : 0.f;
    }
    if (i < KK * CIN * COUT) {
        const int co = i % COUT;
        const int t  = i / COUT;
        const int ci = t % CIN;
        const int k  = t / CIN;
        g_wr[i] = w[(co * CIN + ci) * KK + k];
    }
    if (i < COFF * PP) g_off[i] = __ldg(ob + i / PP);
    if (i < COUT * PP) out[i]   = __ldg(bias + i / PP);
}

// ---------------------------------------------------------------------------
// Transpose x: [ci][v] -> xt[v][ci]
// ---------------------------------------------------------------------------
__global__ __launch_bounds__(256)
void transpose_kernel(const float* __restrict__ x) {
    __shared__ float tile[CIN][33];
    const int v0 = blockIdx.x * 32;
    const int t  = threadIdx.x;
    const int a  = t & 31, g = t >> 5;
#pragma unroll
    for (int cc = 0; cc < CIN; cc += 8)
        tile[cc + g][a] = __ldg(x + (cc + g) * PP + v0 + a);
    __syncthreads();
#pragma unroll
    for (int vv = 0; vv < 32; vv += 8)
        g_xt[(v0 + vv + g) * CIN + a] = tile[a][vv + g];
}

// ---------------------------------------------------------------------------
// Stage 1: dense offset conv, k-split x3, co-distributed weights (R10).
// ---------------------------------------------------------------------------
__global__ __launch_bounds__(128)
void offconv_kernel(const float* __restrict__ x) {
    __shared__ __align__(16) float ws[CIN * OWPAD];   // 12 KB

    const int tid   = threadIdx.x;
    const int lane  = tid & 31;
    const int wbase = blockIdx.x * 128 + (tid >> 5) * 32;
    const int pown  = wbase + lane;
    const int kbase = blockIdx.y * KPG;
    const int pg    = lane & 7;
    const int cg    = lane >> 3;

    const int zo = pown / (HH * WW);
    const int r  = pown - zo * (HH * WW);
    const int yo = r / WW;
    const int xo = r - yo * WW;

    unsigned long long acc2[48];
#pragma unroll
    for (int i = 0; i < 48; i++) acc2[i] = 0ull;

#pragma unroll 1
    for (int kk = 0; kk < KPG; kk++) {
        const int k = kbase + kk;
        __syncthreads();
        {
            const float4* src = (const float4*)(g_owr + k * CIN * OWPAD);
            float4* dst = (float4*)ws;
#pragma unroll
            for (int i = 0; i < 6; i++) dst[tid + 128 * i] = src[tid + 128 * i];
        }
        __syncthreads();

        const int kz = k / 9, ky = (k / 3) % 3, kx = k % 3;
        const int zi = zo + kz - 1, yi = yo + ky - 1, xi = xo + kx - 1;
        const bool valid = ((unsigned)zi < DD) & ((unsigned)yi < HH) & ((unsigned)xi < WW);
        const int xidx = (zi * HH + yi) * WW + xi;

#pragma unroll 2
        for (int ci = 0; ci < CIN; ci++) {
            const float xv_own = valid ? __ldg(x + ci * DHW + xidx) : 0.f;
            unsigned long long xv2[4];
#pragma unroll
            for (int j = 0; j < 4; j++)
                xv2[j] = pack2(__shfl_sync(0xffffffffu, xv_own, 4 * pg + j));
            const ulonglong2* wv = (const ulonglong2*)(ws + ci * OWPAD + 24 * cg);
#pragma unroll
            for (int jj = 0; jj < 6; jj++) {
                const ulonglong2 w2 = wv[jj];
#pragma unroll
                for (int j = 0; j < 4; j++) {
                    acc2[j * 12 + jj * 2 + 0] = fma2(xv2[j], w2.x, acc2[j * 12 + jj * 2 + 0]);
                    acc2[j * 12 + jj * 2 + 1] = fma2(xv2[j], w2.y, acc2[j * 12 + jj * 2 + 1]);
                }
            }
        }
    }

#pragma unroll
    for (int j = 0; j < 4; j++) {
        const int p = wbase + 4 * pg + j;
#pragma unroll
        for (int m = 0; m < 12; m++) {
            float lo, hi;
            unpack2(acc2[j * 12 + m], lo, hi);
            const int c = 24 * cg + 2 * m;
            if (c < COFF)     atomicAdd(g_off + c * PP + p, lo);
            if (c + 1 < COFF) atomicAdd(g_off + (c + 1) * PP + p, hi);
        }
    }
}

// ---------------------------------------------------------------------------
// Stage 2 (fused, k-split x3), co-distributed GEMM phase.
// lane=(pg,cg): thread owns 4 p (wid*32+4pg+j) x 16 co ({8cg..+7} u {32+8cg..+7}).
// stile layout [ci][p] stride 129: conflict-free writes AND reads, warp-local.
// ---------------------------------------------------------------------------
__global__ __launch_bounds__(128, 4)
void deform_fused_kernel(float* __restrict__ out) {
    __shared__ __align__(16) float4 wsm[128][2];       //  4 KB
    __shared__ __align__(16) int4   ism[128][2];       //  4 KB
    __shared__ float stile[CIN * STR];                 // 16.1 KB
    __shared__ __align__(16) float ws[CIN * COUT];     //  8 KB

    const int t     = threadIdx.x;
    const int pbase = blockIdx.x * 128;
    const int p     = pbase + t;
    const int kbase = blockIdx.y * KPG;
    const int wid   = t >> 5, lane = t & 31;
    const int pg    = lane & 7, cg = lane >> 3;
    const int prel  = wid * 32 + 4 * pg;               // own 4 p: prel + j

    const int zo = p / (HH * WW);
    const int r0 = p - zo * (HH * WW);
    const int yo = r0 / WW;
    const int xo = r0 - yo * WW;

    unsigned long long acc2[32];   // [j 0..3][m 0..7]
#pragma unroll
    for (int i = 0; i < 32; i++) acc2[i] = 0ull;

#pragma unroll 1
    for (int kk = 0; kk < KPG; kk++) {
        const int k = kbase + kk;
        __syncthreads();   // everyone done with previous ws before restage

        {   // stage weights [ci][co] for this k
            const float4* src = (const float4*)(g_wr + k * CIN * COUT);
            float4* dst = (float4*)ws;
#pragma unroll
            for (int i = 0; i < 4; i++) dst[t + 128 * i] = src[t + 128 * i];
        }

        {   // geometry for own p -> wsm/ism (warp-local consumers)
            const int kz = k / 9, ky = (k / 3) % 3, kx = k % 3;
            const float dz = __ldg(g_off + (3*k+0) * PP + p);
            const float dy = __ldg(g_off + (3*k+1) * PP + p);
            const float dx = __ldg(g_off + (3*k+2) * PP + p);
            const float zc = (float)(zo + kz - 1) + dz;
            const float yc = (float)(yo + ky - 1) + dy;
            const float xc = (float)(xo + kx - 1) + dx;
            const float zf = floorf(zc), yf = floorf(yc), xf = floorf(xc);
            const float fz = zc - zf, fy = yc - yf, fx = xc - xf;
            const int z0 = (int)zf, y0 = (int)yf, x0 = (int)xf;

            float w8[8]; int id8[8];
#pragma unroll
            for (int j = 0; j < 8; j++) {
                const int dzc = (j >> 2) & 1, dyc = (j >> 1) & 1, dxc = j & 1;
                const int zi = z0 + dzc, yi = y0 + dyc, xi = x0 + dxc;
                const bool v = ((unsigned)zi < DD) & ((unsigned)yi < HH) & ((unsigned)xi < WW);
                const float wz = dzc ? fz : 1.f - fz;
                const float wy = dyc ? fy : 1.f - fy;
                const float wx = dxc ? fx : 1.f - fx;
                w8[j] = v ? (wz * wy * wx) : 0.f;
                const int zic = min(max(zi, 0), DD - 1);
                const int yic = min(max(yi, 0), HH - 1);
                const int xic = min(max(xi, 0), WW - 1);
                id8[j] = ((zic * HH + yic) * WW + xic) * CIN;
            }
            wsm[t][0] = make_float4(w8[0], w8[1], w8[2], w8[3]);
            wsm[t][1] = make_float4(w8[4], w8[5], w8[6], w8[7]);
            ism[t][0] = make_int4(id8[0], id8[1], id8[2], id8[3]);
            ism[t][1] = make_int4(id8[4], id8[5], id8[6], id8[7]);
        }
        __syncthreads();   // ws visible block-wide (wsm/ism warp-local anyway)

        // gather: lane = ci, 8 coalesced 128B-line loads per p
#pragma unroll 4
        for (int pp = 0; pp < 32; pp++) {
            const int tp = wid * 32 + pp;
            const float4 wa = wsm[tp][0], wb = wsm[tp][1];
            const int4   ia = ism[tp][0], ib = ism[tp][1];
            float s;
            s  = wa.x * __ldg(g_xt + ia.x + lane);
            s += wa.y * __ldg(g_xt + ia.y + lane);
            s += wa.z * __ldg(g_xt + ia.z + lane);
            s += wa.w * __ldg(g_xt + ia.w + lane);
            s += wb.x * __ldg(g_xt + ib.x + lane);
            s += wb.y * __ldg(g_xt + ib.y + lane);
            s += wb.z * __ldg(g_xt + ib.z + lane);
            s += wb.w * __ldg(g_xt + ib.w + lane);
            stile[lane * STR + tp] = s;      // banks (lane+tp)%32: conflict-free
        }
        __syncwarp();      // stile producer->consumer is warp-local

        // GEMM: thread owns 4 p x 16 co; all LDS distributed & conflict-free
#pragma unroll 2
        for (int ci = 0; ci < CIN; ci++) {
            const float* srow = stile + ci * STR + prel;
            const unsigned long long s0 = pack2(srow[0]);
            const unsigned long long s1 = pack2(srow[1]);
            const unsigned long long s2 = pack2(srow[2]);
            const unsigned long long s3 = pack2(srow[3]);
            const ulonglong2* wv = (const ulonglong2*)(ws + ci * COUT + 8 * cg);
            const ulonglong2 wA = wv[0];   // co 8cg+0..3
            const ulonglong2 wB = wv[1];   // co 8cg+4..7
            const ulonglong2 wC = wv[8];   // co 32+8cg+0..3
            const ulonglong2 wD = wv[9];   // co 32+8cg+4..7
            acc2[ 0] = fma2(s0, wA.x, acc2[ 0]); acc2[ 1] = fma2(s0, wA.y, acc2[ 1]);
            acc2[ 2] = fma2(s0, wB.x, acc2[ 2]); acc2[ 3] = fma2(s0, wB.y, acc2[ 3]);
            acc2[ 4] = fma2(s0, wC.x, acc2[ 4]); acc2[ 5] = fma2(s0, wC.y, acc2[ 5]);
            acc2[ 6] = fma2(s0, wD.x, acc2[ 6]); acc2[ 7] = fma2(s0, wD.y, acc2[ 7]);
            acc2[ 8] = fma2(s1, wA.x, acc2[ 8]); acc2[ 9] = fma2(s1, wA.y, acc2[ 9]);
            acc2[10] = fma2(s1, wB.x, acc2[10]); acc2[11] = fma2(s1, wB.y, acc2[11]);
            acc2[12] = fma2(s1, wC.x, acc2[12]); acc2[13] = fma2(s1, wC.y, acc2[13]);
            acc2[14] = fma2(s1, wD.x, acc2[14]); acc2[15] = fma2(s1, wD.y, acc2[15]);
            acc2[16] = fma2(s2, wA.x, acc2[16]); acc2[17] = fma2(s2, wA.y, acc2[17]);
            acc2[18] = fma2(s2, wB.x, acc2[18]); acc2[19] = fma2(s2, wB.y, acc2[19]);
            acc2[20] = fma2(s2, wC.x, acc2[20]); acc2[21] = fma2(s2, wC.y, acc2[21]);
            acc2[22] = fma2(s2, wD.x, acc2[22]); acc2[23] = fma2(s2, wD.y, acc2[23]);
            acc2[24] = fma2(s3, wA.x, acc2[24]); acc2[25] = fma2(s3, wA.y, acc2[25]);
            acc2[26] = fma2(s3, wB.x, acc2[26]); acc2[27] = fma2(s3, wB.y, acc2[27]);
            acc2[28] = fma2(s3, wC.x, acc2[28]); acc2[29] = fma2(s3, wC.y, acc2[29]);
            acc2[30] = fma2(s3, wD.x, acc2[30]); acc2[31] = fma2(s3, wD.y, acc2[31]);
        }
        __syncwarp();      // GEMM reads done before next gather rewrites stile
    }

    // epilogue: acc2[j*8+m] -> co = 8cg+2m(+1) for m<4, 32+8cg+2(m-4)(+1) else
#pragma unroll
    for (int j = 0; j < 4; j++) {
        const int pj = pbase + prel + j;
#pragma unroll
        for (int m = 0; m < 8; m++) {
            float lo, hi;
            unpack2(acc2[j * 8 + m], lo, hi);
            const int co = (m < 4) ? (8 * cg + 2 * m) : (32 + 8 * cg + 2 * (m - 4));
            atomicAdd(out + (co + 0) * PP + pj, lo);
            atomicAdd(out + (co + 1) * PP + pj, hi);
        }
    }
}

// ---------------------------------------------------------------------------
extern "C" void kernel_launch(void* const* d_in, const int* in_sizes, int n_in,
                              void* d_out, int out_size) {
    const float* x    = (const float*)d_in[0];  // [32,16,56,56]
    const float* offw = (const float*)d_in[1];  // [81,32,3,3,3]
    const float* offb = (const float*)d_in[2];  // [81]
    const float* w    = (const float*)d_in[3];  // [64,32,3,3,3]
    const float* b    = (const float*)d_in[4];  // [64]
    float* out = (float*)d_out;                 // [64,16,56,56]

    const int initN = (COFF * PP + 255) / 256;
    init_kernel<<<initN, 256>>>(offw, w, offb, b, out);
    transpose_kernel<<<PP / 32, 256>>>(x);
    const dim3 grid2(PP / 128, KSPL);
    offconv_kernel<<<grid2, 128>>>(x);
    deform_fused_kernel<<<grid2, 128>>>(out);
}

// round 16
// speedup vs baseline: 3.3671x; 1.6925x over previous
#include <cuda_runtime.h>
#include <cstdint>

#define DD   16
#define HH   56
#define WW   56
#define PP   (DD*HH*WW)      // 50176
#define CIN  32
#define COUT 64
#define KK   27
#define COFF 81
#define DHW  PP
#define KSPL 3
#define KPG  (KK/KSPL)       // 9
#define SSTR 36              // stile stride (words): 36%32=4 -> A-frag banks perfect
#define WSD  72              // deform B stride: 72%32=8 -> B-frag banks perfect
#define WSO  104             // offconv B stride: 104%32=8
#define OWP  96              // offset channels padded to 96 (12 N-tiles)

__device__ float    g_off [COFF * PP];      // offsets [c][p] (bias-preinit, REDG)
__device__ float    g_xt  [PP * CIN];       // x transposed: [voxel][ci]
__device__ uint32_t g_wr  [KK * CIN * COUT];// main weight tf32 [k][ci][co]
__device__ uint32_t g_owr [KK * CIN * OWP]; // offset weight tf32 [k][ci][c pad96]

__device__ __forceinline__ uint32_t f2tf32(float f) {
    uint32_t u;
    asm("cvt.rna.tf32.f32 %0, %1;" : "=r"(u) : "f"(f));
    return u;
}
__device__ __forceinline__ void mma_tf32(float* d, uint32_t a0, uint32_t a1,
                                         uint32_t a2, uint32_t a3,
                                         uint32_t b0, uint32_t b1) {
    asm("mma.sync.aligned.m16n8k8.row.col.f32.tf32.tf32.f32 "
        "{%0,%1,%2,%3}, {%4,%5,%6,%7}, {%8,%9}, {%0,%1,%2,%3};"
        : "+f"(d[0]), "+f"(d[1]), "+f"(d[2]), "+f"(d[3])
        : "r"(a0), "r"(a1), "r"(a2), "r"(a3), "r"(b0), "r"(b1));
}

// ---------------------------------------------------------------------------
// Init: weights -> tf32 rearranged; preinit g_off (offset bias) and out (bias)
// ---------------------------------------------------------------------------
__global__ void init_kernel(const float* __restrict__ offw,
                            const float* __restrict__ w,
                            const float* __restrict__ ob,
                            const float* __restrict__ bias,
                            float* __restrict__ out) {
    const int i = blockIdx.x * blockDim.x + threadIdx.x;
    if (i < KK * CIN * OWP) {
        const int k = i / (CIN * OWP);
        const int r = i % (CIN * OWP);
        const int ci = r / OWP, c = r % OWP;
        g_owr[i] = (c < COFF) ? f2tf32(offw[(c * CIN + ci) * KK + k]) : 0u;
    }
    if (i < KK * CIN * COUT) {
        const int k = i >> 11;
        const int r = i & 2047;
        const int ci = r >> 6, co = r & 63;
        g_wr[i] = f2tf32(w[(co * CIN + ci) * KK + k]);
    }
    if (i < COFF * PP) g_off[i] = __ldg(ob + i / PP);
    if (i < COUT * PP) out[i]   = __ldg(bias + i / PP);
}

// ---------------------------------------------------------------------------
// Transpose x: [ci][v] -> xt[v][ci]
// ---------------------------------------------------------------------------
__global__ __launch_bounds__(256)
void transpose_kernel(const float* __restrict__ x) {
    __shared__ float tile[CIN][33];
    const int v0 = blockIdx.x * 32;
    const int t  = threadIdx.x;
    const int a  = t & 31, g = t >> 5;
#pragma unroll
    for (int cc = 0; cc < CIN; cc += 8)
        tile[cc + g][a] = __ldg(x + (cc + g) * PP + v0 + a);
    __syncthreads();
#pragma unroll
    for (int vv = 0; vv < 32; vv += 8)
        g_xt[(v0 + vv + g) * CIN + a] = tile[a][vv + g];
}

// ---------------------------------------------------------------------------
// Stage 1: offset conv via tf32 mma.  grid (392, 3).
// A = dense voxel rows from xt (1 coalesced LDG per p), B = offset weights.
// ---------------------------------------------------------------------------
__global__ __launch_bounds__(128, 4)
void offconv_kernel() {
    __shared__ __align__(16) uint32_t stile[128 * SSTR];  // 18.4 KB
    __shared__ __align__(16) uint32_t ws[CIN * WSO];      // 13.3 KB

    const int t     = threadIdx.x;
    const int lane  = t & 31, wid = t >> 5;
    const int woff  = wid * 32;
    const int pbase = blockIdx.x * 128;
    const int p     = pbase + t;
    const int kbase = blockIdx.y * KPG;

    const int zo = p / (HH * WW);
    const int r0 = p - zo * (HH * WW);
    const int yo = r0 / WW;
    const int xo = r0 - yo * WW;

    float acc[2][12][4];
#pragma unroll
    for (int m = 0; m < 2; m++)
#pragma unroll
        for (int nn = 0; nn < 12; nn++)
#pragma unroll
            for (int e = 0; e < 4; e++) acc[m][nn][e] = 0.f;

    const uint32_t* aB = stile + (woff + (lane >> 2)) * SSTR + (lane & 3);
    const uint32_t* bB = ws + (lane & 3) * WSO + (lane >> 2);

#pragma unroll 1
    for (int kk = 0; kk < KPG; kk++) {
        const int k = kbase + kk;
        __syncthreads();
        {   // stage B: 32x96 tf32 -> stride-104 rows, 768 uint4
            const uint4* src = (const uint4*)(g_owr + k * CIN * OWP);
#pragma unroll
            for (int j = 0; j < 6; j++) {
                const int i4 = t + 128 * j;
                const int i  = 4 * i4;
                *(uint4*)(ws + (i / OWP) * WSO + (i % OWP)) = src[i4];
            }
        }
        __syncthreads();

        // own-p neighbor voxel for this k (shift of p), -1 if out of bounds
        const int kz = k / 9, ky = (k / 3) % 3, kx = k % 3;
        const int zi = zo + kz - 1, yi = yo + ky - 1, xi = xo + kx - 1;
        const bool valid = ((unsigned)zi < DD) & ((unsigned)yi < HH) & ((unsigned)xi < WW);
        const int xid_own = valid ? ((zi * HH + yi) * WW + xi) : -1;

        // fill A: one coalesced 128B row per p (lane = ci)
#pragma unroll 4
        for (int pp = 0; pp < 32; pp++) {
            const int xid = __shfl_sync(0xffffffffu, xid_own, pp);
            uint32_t v = 0u;
            if (xid >= 0) v = f2tf32(__ldg(g_xt + xid * CIN + lane));
            stile[(woff + pp) * SSTR + lane] = v;
        }
        __syncwarp();

        // mma: 2 M x 12 N x 4 K tiles
#pragma unroll
        for (int kt = 0; kt < 4; kt++) {
            const uint32_t a00 = aB[8 * kt],            a01 = aB[8 * SSTR + 8 * kt];
            const uint32_t a02 = aB[8 * kt + 4],        a03 = aB[8 * SSTR + 8 * kt + 4];
            const uint32_t a10 = aB[16 * SSTR + 8 * kt],a11 = aB[24 * SSTR + 8 * kt];
            const uint32_t a12 = aB[16 * SSTR + 8 * kt + 4], a13 = aB[24 * SSTR + 8 * kt + 4];
#pragma unroll
            for (int nn = 0; nn < 12; nn++) {
                const uint32_t b0 = bB[(8 * kt) * WSO + 8 * nn];
                const uint32_t b1 = bB[(8 * kt + 4) * WSO + 8 * nn];
                mma_tf32(acc[0][nn], a00, a01, a02, a03, b0, b1);
                mma_tf32(acc[1][nn], a10, a11, a12, a13, b0, b1);
            }
        }
        __syncwarp();
    }

    // epilogue -> g_off (bias-preinit): D row=p, col=c
#pragma unroll
    for (int m = 0; m < 2; m++) {
        const int prow = pbase + woff + 16 * m + (lane >> 2);
#pragma unroll
        for (int nn = 0; nn < 12; nn++) {
            const int c = 8 * nn + 2 * (lane & 3);
            if (c < COFF)     { atomicAdd(g_off + c * PP + prow,     acc[m][nn][0]);
                                atomicAdd(g_off + c * PP + prow + 8, acc[m][nn][2]); }
            if (c + 1 < COFF) { atomicAdd(g_off + (c+1) * PP + prow,     acc[m][nn][1]);
                                atomicAdd(g_off + (c+1) * PP + prow + 8, acc[m][nn][3]); }
        }
    }
}

// ---------------------------------------------------------------------------
// Stage 2: deformable gather (unchanged) + tf32 mma GEMM.  grid (392, 3).
// ---------------------------------------------------------------------------
__global__ __launch_bounds__(128, 4)
void deform_fused_kernel(float* __restrict__ out) {
    __shared__ __align__(16) uint32_t stile[128 * SSTR];  // 18.4 KB
    __shared__ __align__(16) uint32_t ws[CIN * WSD];      //  9.2 KB
    __shared__ __align__(16) float4 wsm[128][2];          //  4 KB
    __shared__ __align__(16) int4   ism[128][2];          //  4 KB

    const int t     = threadIdx.x;
    const int lane  = t & 31, wid = t >> 5;
    const int woff  = wid * 32;
    const int pbase = blockIdx.x * 128;
    const int p     = pbase + t;
    const int kbase = blockIdx.y * KPG;

    const int zo = p / (HH * WW);
    const int r0 = p - zo * (HH * WW);
    const int yo = r0 / WW;
    const int xo = r0 - yo * WW;

    float acc[2][8][4];
#pragma unroll
    for (int m = 0; m < 2; m++)
#pragma unroll
        for (int nn = 0; nn < 8; nn++)
#pragma unroll
            for (int e = 0; e < 4; e++) acc[m][nn][e] = 0.f;

    const uint32_t* aB = stile + (woff + (lane >> 2)) * SSTR + (lane & 3);
    const uint32_t* bB = ws + (lane & 3) * WSD + (lane >> 2);

#pragma unroll 1
    for (int kk = 0; kk < KPG; kk++) {
        const int k = kbase + kk;
        __syncthreads();
        {   // stage B: 32x64 tf32 -> stride-72 rows, 512 uint4
            const uint4* src = (const uint4*)(g_wr + k * 2048);
#pragma unroll
            for (int j = 0; j < 4; j++) {
                const int i4 = t + 128 * j;
                const int i  = 4 * i4;
                *(uint4*)(ws + (i >> 6) * WSD + (i & 63)) = src[i4];
            }
        }

        {   // geometry for own p -> wsm/ism (warp-local consumers)
            const int kz = k / 9, ky = (k / 3) % 3, kx = k % 3;
            const float dz = __ldg(g_off + (3*k+0) * PP + p);
            const float dy = __ldg(g_off + (3*k+1) * PP + p);
            const float dx = __ldg(g_off + (3*k+2) * PP + p);
            const float zc = (float)(zo + kz - 1) + dz;
            const float yc = (float)(yo + ky - 1) + dy;
            const float xc = (float)(xo + kx - 1) + dx;
            const float zf = floorf(zc), yf = floorf(yc), xf = floorf(xc);
            const float fz = zc - zf, fy = yc - yf, fx = xc - xf;
            const int z0 = (int)zf, y0 = (int)yf, x0 = (int)xf;

            float w8[8]; int id8[8];
#pragma unroll
            for (int j = 0; j < 8; j++) {
                const int dzc = (j >> 2) & 1, dyc = (j >> 1) & 1, dxc = j & 1;
                const int zi = z0 + dzc, yi = y0 + dyc, xi = x0 + dxc;
                const bool v = ((unsigned)zi < DD) & ((unsigned)yi < HH) & ((unsigned)xi < WW);
                const float wz = dzc ? fz : 1.f - fz;
                const float wy = dyc ? fy : 1.f - fy;
                const float wx = dxc ? fx : 1.f - fx;
                w8[j] = v ? (wz * wy * wx) : 0.f;
                const int zic = min(max(zi, 0), DD - 1);
                const int yic = min(max(yi, 0), HH - 1);
                const int xic = min(max(xi, 0), WW - 1);
                id8[j] = ((zic * HH + yic) * WW + xic) * CIN;
            }
            wsm[t][0] = make_float4(w8[0], w8[1], w8[2], w8[3]);
            wsm[t][1] = make_float4(w8[4], w8[5], w8[6], w8[7]);
            ism[t][0] = make_int4(id8[0], id8[1], id8[2], id8[3]);
            ism[t][1] = make_int4(id8[4], id8[5], id8[6], id8[7]);
        }
        __syncthreads();   // ws staged; wsm/ism visible (warp-local anyway)

        // gather: lane = ci, 8 coalesced 128B-line loads per p
#pragma unroll 4
        for (int pp = 0; pp < 32; pp++) {
            const int tp = woff + pp;
            const float4 wa = wsm[tp][0], wb = wsm[tp][1];
            const int4   ia = ism[tp][0], ib = ism[tp][1];
            float s;
            s  = wa.x * __ldg(g_xt + ia.x + lane);
            s += wa.y * __ldg(g_xt + ia.y + lane);
            s += wa.z * __ldg(g_xt + ia.z + lane);
            s += wa.w * __ldg(g_xt + ia.w + lane);
            s += wb.x * __ldg(g_xt + ib.x + lane);
            s += wb.y * __ldg(g_xt + ib.y + lane);
            s += wb.z * __ldg(g_xt + ib.z + lane);
            s += wb.w * __ldg(g_xt + ib.w + lane);
            stile[tp * SSTR + lane] = f2tf32(s);
        }
        __syncwarp();

        // mma: 2 M x 8 N x 4 K tiles
#pragma unroll
        for (int kt = 0; kt < 4; kt++) {
            const uint32_t a00 = aB[8 * kt],            a01 = aB[8 * SSTR + 8 * kt];
            const uint32_t a02 = aB[8 * kt + 4],        a03 = aB[8 * SSTR + 8 * kt + 4];
            const uint32_t a10 = aB[16 * SSTR + 8 * kt],a11 = aB[24 * SSTR + 8 * kt];
            const uint32_t a12 = aB[16 * SSTR + 8 * kt + 4], a13 = aB[24 * SSTR + 8 * kt + 4];
#pragma unroll
            for (int nn = 0; nn < 8; nn++) {
                const uint32_t b0 = bB[(8 * kt) * WSD + 8 * nn];
                const uint32_t b1 = bB[(8 * kt + 4) * WSD + 8 * nn];
                mma_tf32(acc[0][nn], a00, a01, a02, a03, b0, b1);
                mma_tf32(acc[1][nn], a10, a11, a12, a13, b0, b1);
            }
        }
        __syncwarp();
    }

    // epilogue -> out (bias-preinit): D row=p, col=co
#pragma unroll
    for (int m = 0; m < 2; m++) {
        const int prow = pbase + woff + 16 * m + (lane >> 2);
#pragma unroll
        for (int nn = 0; nn < 8; nn++) {
            const int co = 8 * nn + 2 * (lane & 3);
            atomicAdd(out + co * PP + prow,           acc[m][nn][0]);
            atomicAdd(out + (co + 1) * PP + prow,     acc[m][nn][1]);
            atomicAdd(out + co * PP + prow + 8,       acc[m][nn][2]);
            atomicAdd(out + (co + 1) * PP + prow + 8, acc[m][nn][3]);
        }
    }
}

// ---------------------------------------------------------------------------
extern "C" void kernel_launch(void* const* d_in, const int* in_sizes, int n_in,
                              void* d_out, int out_size) {
    const float* x    = (const float*)d_in[0];  // [32,16,56,56]
    const float* offw = (const float*)d_in[1];  // [81,32,3,3,3]
    const float* offb = (const float*)d_in[2];  // [81]
    const float* w    = (const float*)d_in[3];  // [64,32,3,3,3]
    const float* b    = (const float*)d_in[4];  // [64]
    float* out = (float*)d_out;                 // [64,16,56,56]

    const int initN = (COFF * PP + 255) / 256;
    init_kernel<<<initN, 256>>>(offw, w, offb, b, out);
    transpose_kernel<<<PP / 32, 256>>>(x);
    const dim3 grid2(PP / 128, KSPL);
    offconv_kernel<<<grid2, 128>>>();
    deform_fused_kernel<<<grid2, 128>>>(out);
}